// round 6
// baseline (speedup 1.0000x reference)
#include <cuda_runtime.h>
#include <cstdint>

#define THREADS  128
#define WPB      4          // warps per block
#define RPB      8          // rows per block (2 per warp, 16-lane halves)
#define NTERMS   16
#define NBUCKETS 64
#define DIM4     128        // 512 floats = 128 float4
#define ROWBYTES 2048       // one row = 512 floats

// Zero at module load; finalizing warp restores zeros each launch
// (graph-replay deterministic, no init kernel).
__device__ double   g_sum[NBUCKETS];
__device__ double   g_cnt[NBUCKETS];
__device__ unsigned g_ticket;
__device__ int      g_flag32;   // 1 => target buffer is int32 (jax demoted)

// C = 255*ln2 + lgamma(256) - 256*ln(2*pi)
#define LOSS_C 867.968103160394f

__device__ __forceinline__ float dot4(float4 a, float4 b) {
    return a.x*b.x + a.y*b.y + a.z*b.z + a.w*b.w;
}
__device__ __forceinline__ unsigned su32(const void* p) {
    return (unsigned)__cvta_generic_to_shared(p);
}

// Detect whether target buffer is int64 or int32. Reads first n/2 int64 words
// = first n*4 bytes, in-bounds for both layouts.
__global__ void nll_detect(const long long* __restrict__ t64, int n_half, long long vocab) {
    int i = blockIdx.x * blockDim.x + threadIdx.x;
    if (i < n_half) {
        long long v = t64[i];
        if (v < 0 || v >= vocab) g_flag32 = 1;   // all writers store 1: race-free
    }
}

__global__ void __launch_bounds__(THREADS)
nll_main(const float* __restrict__ preds,
         const void*  __restrict__ target,
         const float* __restrict__ emb,
         float* __restrict__ out, int out_size, int n, unsigned total_warps)
{
    __shared__ alignas(128) float s_preds[RPB * DIM4 * 4];   // 16 KB
    __shared__ alignas(128) float s_emb[RPB * DIM4 * 4];     // 16 KB
    __shared__ long long s_tgt[RPB];
    __shared__ alignas(8) unsigned long long s_mbar;

    int tid  = threadIdx.x;
    int lane = tid & 31;
    int w    = tid >> 5;
    int row0 = blockIdx.x * RPB;
    int nrows = n - row0; if (nrows > RPB) nrows = RPB;

    if (tid == 0) {
        asm volatile("mbarrier.init.shared.b64 [%0], 1;"
                     :: "r"(su32(&s_mbar)) : "memory");
    }
    __syncthreads();

    // Warp 0: load targets, stage to smem, issue all async bulk copies.
    if (w == 0) {
        long long t_l = 1;   // PAD default; safe emb row
        if (lane < RPB) {
            int r = row0 + lane;
            if (r < n) {
                t_l = g_flag32 ? (long long)((const int*)target)[r]
                               : ((const long long*)target)[r];
            }
            s_tgt[lane] = t_l;
        }
        unsigned mbar = su32(&s_mbar);
        if (lane == 0) {
            unsigned tx = (unsigned)nrows * ROWBYTES + RPB * ROWBYTES;
            asm volatile("mbarrier.arrive.expect_tx.shared.b64 _, [%0], %1;"
                         :: "r"(mbar), "r"(tx) : "memory");
            // Contiguous preds slab for this block's rows.
            asm volatile(
                "cp.async.bulk.shared::cluster.global.mbarrier::complete_tx::bytes "
                "[%0], [%1], %2, [%3];"
                :: "r"(su32(s_preds)),
                   "l"(preds + (size_t)row0 * (DIM4 * 4)),
                   "r"((unsigned)nrows * ROWBYTES), "r"(mbar) : "memory");
        }
        #pragma unroll
        for (int j = 0; j < RPB; j++) {
            long long tj = __shfl_sync(0xffffffffu, t_l, j);
            if (lane == 0) {
                asm volatile(
                    "cp.async.bulk.shared::cluster.global.mbarrier::complete_tx::bytes "
                    "[%0], [%1], %2, [%3];"
                    :: "r"(su32(s_emb) + (unsigned)(j * ROWBYTES)),
                       "l"(emb + (size_t)tj * (DIM4 * 4)),
                       "r"((unsigned)ROWBYTES), "r"(su32(&s_mbar)) : "memory");
            }
        }
    }
    __syncthreads();   // publish s_tgt to all warps

    // Wait for all 9 bulk copies (phase 0; mbar freshly init'd each launch).
    {
        unsigned mbar = su32(&s_mbar);
        asm volatile(
            "{\n\t"
            ".reg .pred P;\n"
            "$wl_%=:\n\t"
            "mbarrier.try_wait.parity.acquire.cta.shared::cta.b64 P, [%0], 0, 0x989680;\n\t"
            "@P bra.uni $wd_%=;\n\t"
            "bra.uni $wl_%=;\n"
            "$wd_%=:\n\t"
            "}"
            :: "r"(mbar) : "memory");
    }

    // Compute: each warp owns 2 rows via 16-lane halves.
    int half = lane >> 4;
    int sub  = lane & 15;
    int r    = w * 2 + half;          // 0..7
    long long t = s_tgt[r];

    const float4* p4 = reinterpret_cast<const float4*>(s_preds) + r * DIM4 + sub;
    const float4* e4 = reinterpret_cast<const float4*>(s_emb)   + r * DIM4 + sub;

    float ss = 0.0f, dt = 0.0f;
    #pragma unroll
    for (int k = 0; k < 8; k++) {
        float4 a = p4[k * 16];
        float4 b = e4[k * 16];
        ss += dot4(a, a);
        dt += dot4(a, b);
    }

    #pragma unroll
    for (int o = 8; o > 0; o >>= 1) {
        ss += __shfl_down_sync(0xffffffffu, ss, o, 16);
        dt += __shfl_down_sync(0xffffffffu, dt, o, 16);
    }

    float loss = 0.0f, cnt = 0.0f;
    if (sub == 0 && t != 1) {   // PAD_ID == 1 (rows >= n were forced to PAD)
        float z = sqrtf(ss);
        float x = 0.25f * ss;
        // S = sum_j x^j / (j! * (256)_j); x ~ 128 => converged well before j=16.
        float S = 1.0f, term = 1.0f;
        #pragma unroll
        for (int j = 1; j < NTERMS; j++) {
            term *= x * (1.0f / ((float)j * (255.0f + (float)j)));
            S += term;
        }
        loss = logf(S) - z - dt - LOSS_C;
        cnt  = 1.0f;
    }
    loss += __shfl_down_sync(0xffffffffu, loss, 16);
    cnt  += __shfl_down_sync(0xffffffffu, cnt,  16);

    unsigned wg = blockIdx.x * WPB + w;
    if (lane == 0) {
        if (cnt > 0.0f) {
            int b = wg & (NBUCKETS - 1);
            atomicAdd(&g_sum[b], (double)loss);
            atomicAdd(&g_cnt[b], (double)cnt);
        }
        __threadfence();               // release before ticket
    }

    // ---- last-WARP finalize + state reset ----
    unsigned tkt = 0;
    if (lane == 0) tkt = atomicAdd(&g_ticket, 1u);
    tkt = __shfl_sync(0xffffffffu, tkt, 0);

    if (tkt == total_warps - 1) {
        __threadfence();               // acquire all blocks' atomics
        double s = g_sum[lane] + g_sum[lane + 32];
        double c = g_cnt[lane] + g_cnt[lane + 32];
        #pragma unroll
        for (int o = 16; o > 0; o >>= 1) {
            s += __shfl_down_sync(0xffffffffu, s, o);
            c += __shfl_down_sync(0xffffffffu, c, o);
        }
        if (lane == 0) {
            float rres = (float)(s / c);
            for (int i = 0; i < out_size; i++) out[i] = rres;
            g_ticket = 0u;
            g_flag32 = 0;
        }
        g_sum[lane] = 0.0; g_sum[lane + 32] = 0.0;
        g_cnt[lane] = 0.0; g_cnt[lane + 32] = 0.0;
    }
}

extern "C" void kernel_launch(void* const* d_in, const int* in_sizes, int n_in,
                              void* d_out, int out_size) {
    const float* preds  = (const float*)d_in[0];
    const void*  target = d_in[1];
    const float* emb    = (const float*)d_in[2];
    int n = in_sizes[1];                              // B*S rows
    long long vocab = (long long)(in_sizes[2] / 512); // rows of emb table

    int nd = n / 2;
    nll_detect<<<(nd + 255) / 256, 256>>>((const long long*)target, nd, vocab);
    int blocks = (n + RPB - 1) / RPB;
    unsigned total_warps = (unsigned)blocks * WPB;
    nll_main<<<blocks, THREADS>>>(preds, target, emb, (float*)d_out,
                                  out_size, n, total_warps);
}

// round 7
// speedup vs baseline: 1.5254x; 1.5254x over previous
#include <cuda_runtime.h>

#define THREADS  256
#define WPB      8          // warps per block
#define RPW      2          // rows per warp (parallel 16-lane halves)
#define RPB      (WPB * RPW)
#define NTERMS   16
#define NBUCKETS 64
#define DIM4     128        // 512 floats = 128 float4

// Zero at module load; finalizing block restores zeros each launch
// (graph-replay deterministic, no init kernel).
__device__ double   g_sum[NBUCKETS];
__device__ double   g_cnt[NBUCKETS];
__device__ unsigned g_ticket;
__device__ int      g_flag32;   // 1 => target buffer is int32 (jax demoted)

// C = 255*ln2 + lgamma(256) - 256*ln(2*pi)
#define LOSS_C 867.968103160394f

__device__ __forceinline__ float dot4(float4 a, float4 b) {
    return a.x*b.x + a.y*b.y + a.z*b.z + a.w*b.w;
}

// Scoped atomics: ordering lives on the instruction, NOT in a fence.
// __threadfence() (gpu scope) emits MEMBAR.GL + CCTL.IVALL (L1 flush) — that
// per-warp flush was the hidden serializer in rounds 2-6. These are flush-free.
__device__ __forceinline__ void red_add_release_f64(double* p, double v) {
    asm volatile("red.add.release.gpu.global.f64 [%0], %1;"
                 :: "l"(p), "d"(v) : "memory");
}
__device__ __forceinline__ unsigned atom_add_acqrel_u32(unsigned* p, unsigned v) {
    unsigned r;
    asm volatile("atom.add.acq_rel.gpu.global.u32 %0, [%1], %2;"
                 : "=r"(r) : "l"(p), "r"(v) : "memory");
    return r;
}
__device__ __forceinline__ double ld_cg_f64(const double* p) {
    double r;
    asm volatile("ld.global.cg.f64 %0, [%1];" : "=d"(r) : "l"(p) : "memory");
    return r;
}
__device__ __forceinline__ void st_cg_f64(double* p, double v) {
    asm volatile("st.global.cg.f64 [%0], %1;" :: "l"(p), "d"(v) : "memory");
}

// Detect whether target buffer is int64 or int32. Reads first n/2 int64 words
// = first n*4 bytes, in-bounds for both layouts.
__global__ void nll_detect(const long long* __restrict__ t64, int n_half, long long vocab) {
    int i = blockIdx.x * blockDim.x + threadIdx.x;
    if (i < n_half) {
        long long v = t64[i];
        if (v < 0 || v >= vocab) g_flag32 = 1;   // all writers store 1: race-free
    }
}

__global__ void __launch_bounds__(THREADS)
nll_main(const float* __restrict__ preds,
         const void*  __restrict__ target,
         const float* __restrict__ emb,
         float* __restrict__ out, int out_size, int n)
{
    int tid   = threadIdx.x;
    int lane  = tid & 31;
    int half  = lane >> 4;          // 0: row0, 1: row1
    int sub   = lane & 15;          // lane within half
    int w     = tid >> 5;
    unsigned wg = blockIdx.x * WPB + w;     // global warp id
    int row   = (int)wg * RPW + half;
    int rowc  = row < n ? row : 0;          // clamp; invalid rows forced to PAD
    int flag  = g_flag32;                   // uniform per warp (L2 broadcast)

    // Lanes 0,1 load the warp's two targets; broadcast to halves.
    long long t_l = 1;
    if (lane < RPW) {
        int r = (int)wg * RPW + lane;
        if (r < n) {
            t_l = flag ? (long long)((const int*)target)[r]
                       : ((const long long*)target)[r];
        }
    }

    // Front-batched preds loads (independent of target).
    const float4* p = reinterpret_cast<const float4*>(preds) + (size_t)rowc * DIM4 + sub;
    float4 a0 = p[0],  a1 = p[16], a2 = p[32], a3 = p[48];
    float4 a4 = p[64], a5 = p[80], a6 = p[96], a7 = p[112];

    long long t = __shfl_sync(0xffffffffu, t_l, half);
    if (row >= n) t = 1;                    // PAD => contributes nothing

    const float4* e = reinterpret_cast<const float4*>(emb) + (size_t)t * DIM4 + sub;
    float4 b0 = e[0],  b1 = e[16], b2 = e[32], b3 = e[48];
    float4 b4 = e[64], b5 = e[80], b6 = e[96], b7 = e[112];

    float ss = dot4(a0,a0)+dot4(a1,a1)+dot4(a2,a2)+dot4(a3,a3)
             + dot4(a4,a4)+dot4(a5,a5)+dot4(a6,a6)+dot4(a7,a7);
    float dt = dot4(a0,b0)+dot4(a1,b1)+dot4(a2,b2)+dot4(a3,b3)
             + dot4(a4,b4)+dot4(a5,b5)+dot4(a6,b6)+dot4(a7,b7);

    // Reduce within each 16-lane half.
    #pragma unroll
    for (int o = 8; o > 0; o >>= 1) {
        ss += __shfl_down_sync(0xffffffffu, ss, o, 16);
        dt += __shfl_down_sync(0xffffffffu, dt, o, 16);
    }

    // Lanes 0 and 16 compute their row's loss SIMD-simultaneously.
    float loss = 0.0f, cnt = 0.0f;
    if (sub == 0 && t != 1) {   // PAD_ID == 1
        float z = sqrtf(ss);
        float x = 0.25f * ss;
        // S = sum_j x^j / (j! * (256)_j); x ~ 128 => converged well before j=16.
        float S = 1.0f, term = 1.0f;
        #pragma unroll
        for (int j = 1; j < NTERMS; j++) {
            term *= x * (1.0f / ((float)j * (255.0f + (float)j)));
            S += term;
        }
        loss = logf(S) - z - dt - LOSS_C;
        cnt  = 1.0f;
    }
    // Fold row1 (lane 16) into lane 0.
    loss += __shfl_down_sync(0xffffffffu, loss, 16);
    cnt  += __shfl_down_sync(0xffffffffu, cnt,  16);

    if (lane == 0 && cnt > 0.0f) {
        int b = wg & (NBUCKETS - 1);
        red_add_release_f64(&g_sum[b], (double)loss);   // release, no L1 flush
        red_add_release_f64(&g_cnt[b], (double)cnt);
    }

    // ---- per-block ticket; last block finalizes + resets state ----
    __syncthreads();
    __shared__ unsigned s_tkt;
    if (tid == 0) s_tkt = atom_add_acqrel_u32(&g_ticket, 1u);
    __syncthreads();

    if (s_tkt == gridDim.x - 1) {
        // acq_rel ticket read synchronized with all blocks' release-reds.
        double s = 0.0, c = 0.0;
        if (tid < NBUCKETS) {                // warps 0,1: L1-bypass loads
            s = ld_cg_f64(&g_sum[tid]);
            c = ld_cg_f64(&g_cnt[tid]);
        }
        #pragma unroll
        for (int o = 16; o > 0; o >>= 1) {
            s += __shfl_down_sync(0xffffffffu, s, o);
            c += __shfl_down_sync(0xffffffffu, c, o);
        }
        __shared__ double sh_s[2], sh_c[2];
        if (tid < NBUCKETS && lane == 0) { sh_s[tid >> 5] = s; sh_c[tid >> 5] = c; }
        __syncthreads();
        if (tid == 0) {
            float r = (float)((sh_s[0] + sh_s[1]) / (sh_c[0] + sh_c[1]));
            for (int i = 0; i < out_size; i++) out[i] = r;
            g_ticket = 0u;
            g_flag32 = 0;
        }
        if (tid < NBUCKETS) {                // reset for next graph replay
            st_cg_f64(&g_sum[tid], 0.0);
            st_cg_f64(&g_cnt[tid], 0.0);
        }
    }
}

extern "C" void kernel_launch(void* const* d_in, const int* in_sizes, int n_in,
                              void* d_out, int out_size) {
    const float* preds  = (const float*)d_in[0];
    const void*  target = d_in[1];
    const float* emb    = (const float*)d_in[2];
    int n = in_sizes[1];                              // B*S rows
    long long vocab = (long long)(in_sizes[2] / 512); // rows of emb table

    int nd = n / 2;
    nll_detect<<<(nd + 255) / 256, 256>>>((const long long*)target, nd, vocab);
    int blocks = (n + RPB - 1) / RPB;
    nll_main<<<blocks, THREADS>>>(preds, target, emb, (float*)d_out, out_size, n);
}

// round 8
// speedup vs baseline: 1.5517x; 1.0172x over previous
#include <cuda_runtime.h>

#define THREADS  256
#define WPB      8          // warps per block
#define RPW      2          // rows per warp (parallel 16-lane halves)
#define RPB      (WPB * RPW)
#define NTERMS   16
#define NBUCKETS 64
#define DIM4     128        // 512 floats = 128 float4

// Buckets padded to one 128-B L2 line each: [b][0]=sum, [b][1]=cnt.
// Zero at module load; finalizing block restores zeros each launch.
__device__ double   g_acc[NBUCKETS][16];
__device__ unsigned g_ticket;
__device__ int      g_flag32;   // 1 => target buffer is int32 (jax demoted)

// C = 255*ln2 + lgamma(256) - 256*ln(2*pi)
#define LOSS_C 867.968103160394f

__device__ __forceinline__ float dot4(float4 a, float4 b) {
    return a.x*b.x + a.y*b.y + a.z*b.z + a.w*b.w;
}

// Scoped atomics: ordering on the instruction, no fence / L1 flush.
__device__ __forceinline__ void red_add_release_f64(double* p, double v) {
    asm volatile("red.add.release.gpu.global.f64 [%0], %1;"
                 :: "l"(p), "d"(v) : "memory");
}
__device__ __forceinline__ unsigned atom_add_acqrel_u32(unsigned* p, unsigned v) {
    unsigned r;
    asm volatile("atom.add.acq_rel.gpu.global.u32 %0, [%1], %2;"
                 : "=r"(r) : "l"(p), "r"(v) : "memory");
    return r;
}
__device__ __forceinline__ double ld_cg_f64(const double* p) {
    double r;
    asm volatile("ld.global.cg.f64 %0, [%1];" : "=d"(r) : "l"(p) : "memory");
    return r;
}
__device__ __forceinline__ void st_cg_f64(double* p, double v) {
    asm volatile("st.global.cg.f64 [%0], %1;" :: "l"(p), "d"(v) : "memory");
}

// Detect whether target buffer is int64 or int32. Reads first n/2 int64 words
// = first n*4 bytes, in-bounds for both layouts.
__global__ void nll_detect(const long long* __restrict__ t64, int n_half, long long vocab) {
    int i = blockIdx.x * blockDim.x + threadIdx.x;
    if (i < n_half) {
        long long v = t64[i];
        if (v < 0 || v >= vocab) g_flag32 = 1;   // all writers store 1: race-free
    }
}

__global__ void __launch_bounds__(THREADS, 2)   // 128-reg budget: keep 16 LDG.128 in flight
nll_main(const float* __restrict__ preds,
         const void*  __restrict__ target,
         const float* __restrict__ emb,
         float* __restrict__ out, int out_size, int n)
{
    int tid   = threadIdx.x;
    int lane  = tid & 31;
    int half  = lane >> 4;          // 0: row0, 1: row1
    int sub   = lane & 15;          // lane within half
    int w     = tid >> 5;
    unsigned wg = blockIdx.x * WPB + w;     // global warp id
    int row   = (int)wg * RPW + half;
    int rowc  = row < n ? row : 0;          // clamp; invalid rows forced to PAD
    int flag  = g_flag32;                   // uniform per warp

    // Lanes 0,1 load the warp's two targets; broadcast to halves.
    long long t_l = 1;
    if (lane < RPW) {
        int r = (int)wg * RPW + lane;
        if (r < n) {
            t_l = flag ? (long long)((const int*)target)[r]
                       : ((const long long*)target)[r];
        }
    }

    // Front-batched preds loads (independent of target) — 8 LDG.128 in flight.
    const float4* p = reinterpret_cast<const float4*>(preds) + (size_t)rowc * DIM4 + sub;
    float4 a0 = p[0],  a1 = p[16], a2 = p[32], a3 = p[48];
    float4 a4 = p[64], a5 = p[80], a6 = p[96], a7 = p[112];

    long long t = __shfl_sync(0xffffffffu, t_l, half);
    if (row >= n) t = 1;                    // PAD => contributes nothing

    // 8 more LDG.128 — with the 128-reg budget all 16 stay outstanding.
    const float4* e = reinterpret_cast<const float4*>(emb) + (size_t)t * DIM4 + sub;
    float4 b0 = e[0],  b1 = e[16], b2 = e[32], b3 = e[48];
    float4 b4 = e[64], b5 = e[80], b6 = e[96], b7 = e[112];

    float ss = dot4(a0,a0)+dot4(a1,a1)+dot4(a2,a2)+dot4(a3,a3)
             + dot4(a4,a4)+dot4(a5,a5)+dot4(a6,a6)+dot4(a7,a7);
    float dt = dot4(a0,b0)+dot4(a1,b1)+dot4(a2,b2)+dot4(a3,b3)
             + dot4(a4,b4)+dot4(a5,b5)+dot4(a6,b6)+dot4(a7,b7);

    // Reduce within each 16-lane half.
    #pragma unroll
    for (int o = 8; o > 0; o >>= 1) {
        ss += __shfl_down_sync(0xffffffffu, ss, o, 16);
        dt += __shfl_down_sync(0xffffffffu, dt, o, 16);
    }

    // Lanes 0 and 16 compute their row's loss SIMD-simultaneously.
    float loss = 0.0f, cnt = 0.0f;
    if (sub == 0 && t != 1) {   // PAD_ID == 1
        float z = sqrtf(ss);
        float x = 0.25f * ss;
        // S = sum_j x^j / (j! * (256)_j); x ~ 128 => converged well before j=16.
        float S = 1.0f, term = 1.0f;
        #pragma unroll
        for (int j = 1; j < NTERMS; j++) {
            term *= x * (1.0f / ((float)j * (255.0f + (float)j)));
            S += term;
        }
        loss = logf(S) - z - dt - LOSS_C;
        cnt  = 1.0f;
    }
    // Fold row1 (lane 16) into lane 0.
    loss += __shfl_down_sync(0xffffffffu, loss, 16);
    cnt  += __shfl_down_sync(0xffffffffu, cnt,  16);

    // ---- block-level reduction: exactly 2 global reds per block ----
    __shared__ float sh_loss[WPB], sh_cnt[WPB];
    if (lane == 0) { sh_loss[w] = loss; sh_cnt[w] = cnt; }
    __syncthreads();

    __shared__ unsigned s_tkt;
    if (tid == 0) {
        float L = 0.0f, C = 0.0f;
        #pragma unroll
        for (int i = 0; i < WPB; i++) { L += sh_loss[i]; C += sh_cnt[i]; }
        int b = blockIdx.x & (NBUCKETS - 1);
        red_add_release_f64(&g_acc[b][0], (double)L);   // release; distinct L2 line per bucket
        red_add_release_f64(&g_acc[b][1], (double)C);
        s_tkt = atom_add_acqrel_u32(&g_ticket, 1u);
    }
    __syncthreads();

    // ---- last block finalizes + resets state ----
    if (s_tkt == gridDim.x - 1) {
        double s = 0.0, c = 0.0;
        if (tid < NBUCKETS) {                // warps 0,1: L1-bypass loads
            s = ld_cg_f64(&g_acc[tid][0]);
            c = ld_cg_f64(&g_acc[tid][1]);
        }
        #pragma unroll
        for (int o = 16; o > 0; o >>= 1) {
            s += __shfl_down_sync(0xffffffffu, s, o);
            c += __shfl_down_sync(0xffffffffu, c, o);
        }
        __shared__ double sh_s[2], sh_c[2];
        if (tid < NBUCKETS && lane == 0) { sh_s[tid >> 5] = s; sh_c[tid >> 5] = c; }
        __syncthreads();
        if (tid == 0) {
            float r = (float)((sh_s[0] + sh_s[1]) / (sh_c[0] + sh_c[1]));
            for (int i = 0; i < out_size; i++) out[i] = r;
            g_ticket = 0u;
            g_flag32 = 0;
        }
        if (tid < NBUCKETS) {                // reset for next graph replay
            st_cg_f64(&g_acc[tid][0], 0.0);
            st_cg_f64(&g_acc[tid][1], 0.0);
        }
    }
}

extern "C" void kernel_launch(void* const* d_in, const int* in_sizes, int n_in,
                              void* d_out, int out_size) {
    const float* preds  = (const float*)d_in[0];
    const void*  target = d_in[1];
    const float* emb    = (const float*)d_in[2];
    int n = in_sizes[1];                              // B*S rows
    long long vocab = (long long)(in_sizes[2] / 512); // rows of emb table

    int nd = n / 2;
    nll_detect<<<(nd + 255) / 256, 256>>>((const long long*)target, nd, vocab);
    int blocks = (n + RPB - 1) / RPB;
    nll_main<<<blocks, THREADS>>>(preds, target, emb, (float*)d_out, out_size, n);
}